// round 8
// baseline (speedup 1.0000x reference)
#include <cuda_runtime.h>
#include <cstdint>

#define N_NODES 100000
#define E_EDGES 1600000
#define D_IN   64
#define D_HID  64
#define D_OUT  40
#define BN_EPS 1e-5f
#define ELL_W  64   // max degree capacity; P(deg>63) ~ 1e-20 for Poisson(16)

// ---------------- scratch (float4 => 16B aligned) ----------------
__device__ float4 g_y[(size_t)N_NODES * 16];      // x @ W1l.T   (projected, per source)
__device__ float4 g_t[(size_t)N_NODES * 16];      // x @ W1r.T + b1
__device__ float4 g_h[(size_t)N_NODES * 16];      // t + mean(y_neigh)  (pre-BN h)
__device__ float4 g_p[(size_t)N_NODES * 10];      // relu(bn(h)) @ W2l.T
__device__ int    g_adj[(size_t)N_NODES * ELL_W]; // ELL adjacency
__device__ int    g_cnt[N_NODES];
__device__ float  g_sum[D_HID];
__device__ float  g_sumsq[D_HID];

// Weights in __device__ globals (coalesced LDG -> smem staging per block)
__device__ float4 g_W1[2048];   // [0:1024) = W1l rows, [1024:2048) = W1r rows
__device__ float4 g_W2[1280];   // [0:640)  = W2l rows, [640:1280)  = W2r rows
__constant__ float c_b1[D_HID];
__constant__ float c_b2[D_OUT];

// ---------------- packed fp32x2 helpers (FFMA2) ----------------
__device__ __forceinline__ void ffma2(unsigned long long& acc,
                                      unsigned long long a,
                                      unsigned long long b) {
    asm("fma.rn.f32x2 %0, %1, %2, %0;" : "+l"(acc) : "l"(a), "l"(b));
}
__device__ __forceinline__ unsigned long long pack2(float lo, float hi) {
    unsigned long long r;
    asm("mov.b64 %0, {%1, %2};" : "=l"(r) : "f"(lo), "f"(hi));
    return r;
}
__device__ __forceinline__ float2 unpack2(unsigned long long v) {
    float2 r;
    asm("mov.b64 {%0, %1}, %2;" : "=f"(r.x), "=f"(r.y) : "l"(v));
    return r;
}

// ---------------- init ----------------
__global__ void k_zero() {
    int i = blockIdx.x * blockDim.x + threadIdx.x;
    int stride = gridDim.x * blockDim.x;
    for (int t = i; t < N_NODES; t += stride) g_cnt[t] = 0;
    if (i < D_HID) { g_sum[i] = 0.f; g_sumsq[i] = 0.f; }
}

// ---------------- single-pass ELL build ----------------
__global__ void k_countfill(const int* __restrict__ src, const int* __restrict__ dst) {
    int t = blockIdx.x * blockDim.x + threadIdx.x;
    int e = t * 8;
    if (e + 8 <= E_EDGES) {
        int4 da = *reinterpret_cast<const int4*>(dst + e);
        int4 db = *reinterpret_cast<const int4*>(dst + e + 4);
        int4 sa = *reinterpret_cast<const int4*>(src + e);
        int4 sb = *reinterpret_cast<const int4*>(src + e + 4);
        int p0 = atomicAdd(&g_cnt[da.x], 1);
        int p1 = atomicAdd(&g_cnt[da.y], 1);
        int p2 = atomicAdd(&g_cnt[da.z], 1);
        int p3 = atomicAdd(&g_cnt[da.w], 1);
        int p4 = atomicAdd(&g_cnt[db.x], 1);
        int p5 = atomicAdd(&g_cnt[db.y], 1);
        int p6 = atomicAdd(&g_cnt[db.z], 1);
        int p7 = atomicAdd(&g_cnt[db.w], 1);
        if (p0 < ELL_W) g_adj[(size_t)da.x * ELL_W + p0] = sa.x;
        if (p1 < ELL_W) g_adj[(size_t)da.y * ELL_W + p1] = sa.y;
        if (p2 < ELL_W) g_adj[(size_t)da.z * ELL_W + p2] = sa.z;
        if (p3 < ELL_W) g_adj[(size_t)da.w * ELL_W + p3] = sa.w;
        if (p4 < ELL_W) g_adj[(size_t)db.x * ELL_W + p4] = sb.x;
        if (p5 < ELL_W) g_adj[(size_t)db.y * ELL_W + p5] = sb.y;
        if (p6 < ELL_W) g_adj[(size_t)db.z * ELL_W + p6] = sb.z;
        if (p7 < ELL_W) g_adj[(size_t)db.w * ELL_W + p7] = sb.w;
    } else {
        for (int k = e; k < E_EDGES; k++) {
            int d = dst[k];
            int pos = atomicAdd(&g_cnt[d], 1);
            if (pos < ELL_W) g_adj[(size_t)d * ELL_W + pos] = src[k];
        }
    }
}

// ---------------- layer-1 projections: y = x@W1l.T, t = x@W1r.T + b1 --------
// Input per thread: one x row (64 floats). Weights staged in smem.
__global__ __launch_bounds__(256) void k_proj1(const float4* __restrict__ x) {
    __shared__ float4 s_W[2048];   // 32KB: W1l rows then W1r rows
#pragma unroll
    for (int t = 0; t < 8; t++) s_W[threadIdx.x + t * 256] = g_W1[threadIdx.x + t * 256];
    __syncthreads();
    int n = blockIdx.x * 256 + threadIdx.x;
    if (n >= N_NODES) return;
    ulonglong2 xv[16];
    const ulonglong2* xp = reinterpret_cast<const ulonglong2*>(x + (size_t)n * 16);
#pragma unroll
    for (int c = 0; c < 16; c++) xv[c] = xp[c];
    const ulonglong2* wl64 = reinterpret_cast<const ulonglong2*>(s_W);
    const ulonglong2* wr64 = reinterpret_cast<const ulonglong2*>(s_W + 1024);
    float4* yp = g_y + (size_t)n * 16;
    float4* tp = g_t + (size_t)n * 16;
    float yj[4], tj[4];
#pragma unroll 1
    for (int jb = 0; jb < 16; jb++) {
#pragma unroll
        for (int u = 0; u < 4; u++) {
            int j = jb * 4 + u;
            unsigned long long a0 = 0ull, a1 = 0ull;                 // y accum
            unsigned long long b0 = pack2(c_b1[j], 0.f), b1 = 0ull;  // t accum
#pragma unroll
            for (int c = 0; c < 16; c++) {
                ulonglong2 wl = wl64[j * 16 + c];
                ulonglong2 wr = wr64[j * 16 + c];
                ffma2(a0, wl.x, xv[c].x);
                ffma2(a1, wl.y, xv[c].y);
                ffma2(b0, wr.x, xv[c].x);
                ffma2(b1, wr.y, xv[c].y);
            }
            float2 f0 = unpack2(a0), f1 = unpack2(a1);
            float2 g0 = unpack2(b0), g1 = unpack2(b1);
            yj[u] = (f0.x + f0.y) + (f1.x + f1.y);
            tj[u] = (g0.x + g0.y) + (g1.x + g1.y);
        }
        yp[jb] = make_float4(yj[0], yj[1], yj[2], yj[3]);
        tp[jb] = make_float4(tj[0], tj[1], tj[2], tj[3]);
    }
}

// ---- h = t + mean(y_neigh); fused BN column stats (block reduce) ----
// Block = 256 threads = 8 warps; warp covers 2 nodes/iter x 4 iters = 64 nodes/block.
__global__ __launch_bounds__(256) void k_agg1h() {
    int warp = threadIdx.x >> 5;
    int lane = threadIdx.x & 31;
    int sub = lane >> 4;
    int q = lane & 15;
    float4 sacc = make_float4(0.f, 0.f, 0.f, 0.f);
    float4 qacc = make_float4(0.f, 0.f, 0.f, 0.f);
    int n0 = blockIdx.x * 64;
#pragma unroll 1
    for (int it = 0; it < 4; it++) {
        int n = n0 + it * 16 + warp * 2 + sub;
        if (n >= N_NODES) continue;
        const int* row = g_adj + (size_t)n * ELL_W;
        int cnt = g_cnt[n];
        if (cnt > ELL_W) cnt = ELL_W;
        float4 acc = make_float4(0.f, 0.f, 0.f, 0.f);
        int i = 0;
        for (; i + 4 <= cnt; i += 4) {
            int4 s4 = *reinterpret_cast<const int4*>(row + i);
            float4 v0 = g_y[(size_t)s4.x * 16 + q];
            float4 v1 = g_y[(size_t)s4.y * 16 + q];
            float4 v2 = g_y[(size_t)s4.z * 16 + q];
            float4 v3 = g_y[(size_t)s4.w * 16 + q];
            acc.x += (v0.x + v1.x) + (v2.x + v3.x);
            acc.y += (v0.y + v1.y) + (v2.y + v3.y);
            acc.z += (v0.z + v1.z) + (v2.z + v3.z);
            acc.w += (v0.w + v1.w) + (v2.w + v3.w);
        }
        for (; i < cnt; i++) {
            int s = row[i];
            float4 v = g_y[(size_t)s * 16 + q];
            acc.x += v.x; acc.y += v.y; acc.z += v.z; acc.w += v.w;
        }
        float inv = 1.0f / (float)(cnt > 0 ? cnt : 1);
        float4 t = g_t[(size_t)n * 16 + q];
        float4 h;
        h.x = fmaf(acc.x, inv, t.x);
        h.y = fmaf(acc.y, inv, t.y);
        h.z = fmaf(acc.z, inv, t.z);
        h.w = fmaf(acc.w, inv, t.w);
        g_h[(size_t)n * 16 + q] = h;
        sacc.x += h.x; sacc.y += h.y; sacc.z += h.z; sacc.w += h.w;
        qacc.x += h.x * h.x; qacc.y += h.y * h.y; qacc.z += h.z * h.z; qacc.w += h.w * h.w;
    }
    // block reduction over threads sharing column group q = threadIdx.x & 15
    __shared__ float4 ssum[256];
    __shared__ float4 ssq[256];
    ssum[threadIdx.x] = sacc;
    ssq[threadIdx.x] = qacc;
    __syncthreads();
    for (int stride = 128; stride >= 16; stride >>= 1) {
        if (threadIdx.x < stride) {
            float4 a = ssum[threadIdx.x + stride];
            float4 b = ssq[threadIdx.x + stride];
            float4 sa = ssum[threadIdx.x];
            float4 sb = ssq[threadIdx.x];
            sa.x += a.x; sa.y += a.y; sa.z += a.z; sa.w += a.w;
            sb.x += b.x; sb.y += b.y; sb.z += b.z; sb.w += b.w;
            ssum[threadIdx.x] = sa;
            ssq[threadIdx.x] = sb;
        }
        __syncthreads();
    }
    if (threadIdx.x < 16) {
        float4 sa = ssum[threadIdx.x];
        float4 sb = ssq[threadIdx.x];
        int jb = threadIdx.x * 4;
        atomicAdd(&g_sum[jb + 0], sa.x);
        atomicAdd(&g_sum[jb + 1], sa.y);
        atomicAdd(&g_sum[jb + 2], sa.z);
        atomicAdd(&g_sum[jb + 3], sa.w);
        atomicAdd(&g_sumsq[jb + 0], sb.x);
        atomicAdd(&g_sumsq[jb + 1], sb.y);
        atomicAdd(&g_sumsq[jb + 2], sb.z);
        atomicAdd(&g_sumsq[jb + 3], sb.w);
    }
}

// ---- BN finalize + ReLU + both layer-2 projections (smem weights) ----
__global__ __launch_bounds__(256) void k_bnrelu_proj(float4* __restrict__ out,
                                                     const float* __restrict__ gamma,
                                                     const float* __restrict__ beta) {
    __shared__ float4 s_W2[1280];   // 20KB
    __shared__ float4 s_scale[16];
    __shared__ float4 s_shift[16];
#pragma unroll
    for (int t = 0; t < 5; t++) s_W2[threadIdx.x + t * 256] = g_W2[threadIdx.x + t * 256];
    if (threadIdx.x < D_HID) {
        int j = threadIdx.x;
        float mu = g_sum[j] * (1.0f / (float)N_NODES);
        float var = g_sumsq[j] * (1.0f / (float)N_NODES) - mu * mu;
        float rs = rsqrtf(var + BN_EPS);
        float sc = gamma[j] * rs;
        reinterpret_cast<float*>(s_scale)[j] = sc;
        reinterpret_cast<float*>(s_shift)[j] = beta[j] - mu * sc;
    }
    __syncthreads();
    int n = blockIdx.x * 256 + threadIdx.x;
    if (n >= N_NODES) return;
    float4 hv[16];
    const float4* hp = g_h + (size_t)n * 16;
#pragma unroll
    for (int c = 0; c < 16; c++) {
        float4 sc = s_scale[c];
        float4 sh = s_shift[c];
        float4 h = hp[c];
        h.x = fmaxf(fmaf(h.x, sc.x, sh.x), 0.f);
        h.y = fmaxf(fmaf(h.y, sc.y, sh.y), 0.f);
        h.z = fmaxf(fmaf(h.z, sc.z, sh.z), 0.f);
        h.w = fmaxf(fmaf(h.w, sc.w, sh.w), 0.f);
        hv[c] = h;
    }
    const ulonglong2* hv64 = reinterpret_cast<const ulonglong2*>(hv);
    const ulonglong2* wl64 = reinterpret_cast<const ulonglong2*>(s_W2);
    const ulonglong2* wr64 = reinterpret_cast<const ulonglong2*>(s_W2 + 640);
    float4* pp = g_p + (size_t)n * 10;
    float4* op = out + (size_t)n * 10;
    float pj[4], oj[4];
#pragma unroll 1
    for (int jb = 0; jb < 10; jb++) {
#pragma unroll
        for (int u = 0; u < 4; u++) {
            int j = jb * 4 + u;
            unsigned long long a0 = 0ull, a1 = 0ull;
            unsigned long long b0 = pack2(c_b2[j], 0.f), b1 = 0ull;
#pragma unroll
            for (int c = 0; c < 16; c++) {
                ulonglong2 wl = wl64[j * 16 + c];
                ulonglong2 wr = wr64[j * 16 + c];
                ffma2(a0, wl.x, hv64[c].x);
                ffma2(a1, wl.y, hv64[c].y);
                ffma2(b0, wr.x, hv64[c].x);
                ffma2(b1, wr.y, hv64[c].y);
            }
            float2 f0 = unpack2(a0), f1 = unpack2(a1);
            float2 g0 = unpack2(b0), g1 = unpack2(b1);
            pj[u] = (f0.x + f0.y) + (f1.x + f1.y);
            oj[u] = (g0.x + g0.y) + (g1.x + g1.y);
        }
        pp[jb] = make_float4(pj[0], pj[1], pj[2], pj[3]);
        op[jb] = make_float4(oj[0], oj[1], oj[2], oj[3]);
    }
}

// ------- aggregation 2: out[n] += mean of neighbor p (40-dim) -------
__global__ __launch_bounds__(256) void k_agg2(float4* __restrict__ out) {
    int gw = (blockIdx.x * blockDim.x + threadIdx.x) >> 5;
    int lane = threadIdx.x & 31;
    int sub = lane / 10;
    int q = lane - sub * 10;
    int n = gw * 3 + sub;
    if (sub >= 3 || n >= N_NODES) return;
    const int* row = g_adj + (size_t)n * ELL_W;
    int cnt = g_cnt[n];
    if (cnt > ELL_W) cnt = ELL_W;
    float4 acc = make_float4(0.f, 0.f, 0.f, 0.f);
    int i = 0;
    for (; i + 4 <= cnt; i += 4) {
        int4 s4 = *reinterpret_cast<const int4*>(row + i);
        float4 v0 = g_p[(size_t)s4.x * 10 + q];
        float4 v1 = g_p[(size_t)s4.y * 10 + q];
        float4 v2 = g_p[(size_t)s4.z * 10 + q];
        float4 v3 = g_p[(size_t)s4.w * 10 + q];
        acc.x += (v0.x + v1.x) + (v2.x + v3.x);
        acc.y += (v0.y + v1.y) + (v2.y + v3.y);
        acc.z += (v0.z + v1.z) + (v2.z + v3.z);
        acc.w += (v0.w + v1.w) + (v2.w + v3.w);
    }
    for (; i < cnt; i++) {
        int s = row[i];
        float4 v = g_p[(size_t)s * 10 + q];
        acc.x += v.x; acc.y += v.y; acc.z += v.z; acc.w += v.w;
    }
    float inv = 1.0f / (float)(cnt > 0 ? cnt : 1);
    float4 o = out[(size_t)n * 10 + q];
    o.x += acc.x * inv; o.y += acc.y * inv; o.z += acc.z * inv; o.w += acc.w * inv;
    out[(size_t)n * 10 + q] = o;
}

// ---------------- launch ----------------
extern "C" void kernel_launch(void* const* d_in, const int* in_sizes, int n_in,
                              void* d_out, int out_size) {
    const float4* x     = (const float4*)d_in[0];
    const int*    ei    = (const int*)d_in[1];   // int32 (jax x64 disabled)
    const float*  gamma = (const float*)d_in[5];
    const float*  beta  = (const float*)d_in[6];
    const int* src = ei;
    const int* dst = ei + E_EDGES;

    cudaMemcpyToSymbolAsync(g_W1, d_in[2], D_HID * D_IN * sizeof(float), 0,     cudaMemcpyDeviceToDevice, 0);
    cudaMemcpyToSymbolAsync(g_W1, d_in[3], D_HID * D_IN * sizeof(float), 16384, cudaMemcpyDeviceToDevice, 0);
    cudaMemcpyToSymbolAsync(c_b1, d_in[4], D_HID * sizeof(float), 0,            cudaMemcpyDeviceToDevice, 0);
    cudaMemcpyToSymbolAsync(g_W2, d_in[7], D_OUT * D_HID * sizeof(float), 0,     cudaMemcpyDeviceToDevice, 0);
    cudaMemcpyToSymbolAsync(g_W2, d_in[8], D_OUT * D_HID * sizeof(float), 10240, cudaMemcpyDeviceToDevice, 0);
    cudaMemcpyToSymbolAsync(c_b2, d_in[9], D_OUT * sizeof(float), 0,             cudaMemcpyDeviceToDevice, 0);

    // ELL adjacency build (shared by both layers)
    k_zero<<<256, 256>>>();
    k_countfill<<<(E_EDGES / 8 + 255) / 256, 256>>>(src, dst);

    // Layer 1: project all nodes, then gather (+fused BN stats)
    k_proj1<<<(N_NODES + 255) / 256, 256>>>(x);
    k_agg1h<<<(N_NODES + 63) / 64, 256>>>();

    // BN finalize + ReLU + layer-2 projections
    k_bnrelu_proj<<<(N_NODES + 255) / 256, 256>>>((float4*)d_out, gamma, beta);

    // Layer 2: add neighbor-mean of p into out
    k_agg2<<<(N_NODES / 3 + 8) / 8, 256>>>((float4*)d_out);
}